// round 8
// baseline (speedup 1.0000x reference)
#include <cuda_runtime.h>
#include <cuda_bf16.h>
#include <cstdint>

// Problem constants (fixed shapes)
#define NN 4096
#define FF 128
#define HEADS 8
#define UU 8
#define NCOL 160        // 80 hi cols + 80 lo cols
#define MT 128          // GEMM M-tile
#define KSPLIT 4        // K-splits
#define KPC 1024        // K per CTA
#define KC 32           // K chunk per pipeline stage
#define NCHUNK (KPC / KC)   // 32
#define SSTR 40         // smem K-stride (elements)

#define ASTG (MT * SSTR * 2)     // 10240 B per A stage
#define BSTG (NCOL * SSTR * 2)   // 12800 B per B stage
#define BBASE (2 * ASTG)         // B ring starts after 2 A stages
#define GEMM_SMEM (2 * ASTG + 4 * BSTG)   // 71680 B

// ---------------- device scratch (no allocations allowed) ----------------
__device__ __align__(128) __nv_bfloat16 g_Xp[NCOL * NN];   // [col][node]
__device__ __align__(128) float g_el[HEADS * NN];
__device__ __align__(128) float g_part[KSPLIT][NN][NCOL];  // 10.5 MB partials

// ---------------- helpers ----------------
__device__ __forceinline__ uint32_t smem_u32(const void* p) {
    uint32_t a;
    asm("{ .reg .u64 t; cvta.to.shared.u64 t, %1; cvt.u32.u64 %0, t; }" : "=r"(a) : "l"(p));
    return a;
}
__device__ __forceinline__ void cpasync8(uint32_t dst, const void* src) {
    asm volatile("cp.async.ca.shared.global [%0], [%1], 8;" :: "r"(dst), "l"(src) : "memory");
}
__device__ __forceinline__ void mma16816v(float c[4], uint32_t a0, uint32_t a1,
                                          uint32_t a2, uint32_t a3,
                                          uint32_t b0, uint32_t b1)
{
    asm volatile(
        "mma.sync.aligned.m16n8k16.row.col.f32.bf16.bf16.f32 "
        "{%0,%1,%2,%3}, {%4,%5,%6,%7}, {%8,%9}, {%0,%1,%2,%3};\n"
        : "+f"(c[0]), "+f"(c[1]), "+f"(c[2]), "+f"(c[3])
        : "r"(a0), "r"(a1), "r"(a2), "r"(a3), "r"(b0), "r"(b1));
}

// ---------------- prep kernel: build Xp and e_l ----------------
// block 256 = 8 warps (one head each) x 32 nodes (one per lane); grid 128
__global__ __launch_bounds__(256) void gat_build(
    const float* __restrict__ H, const float* __restrict__ W,
    const float* __restrict__ al, const float* __restrict__ ar)
{
    __shared__ float sH[32 * 129];    // 16.5 KB, stride 129 -> conflict-free
    const int tid = threadIdx.x;
    const int lane = tid & 31;
    const int h = tid >> 5;
    const int nodeBase = blockIdx.x * 32;

    for (int i = tid; i < 32 * FF; i += 256) {
        int nn = i >> 7, f = i & 127;
        sH[nn * 129 + f] = H[(size_t)(nodeBase + nn) * FF + f];
    }
    __syncthreads();

    const int n = nodeBase + lane;
    float hw[8];
#pragma unroll
    for (int u = 0; u < 8; u++) hw[u] = 0.f;

    const float4* Wp = reinterpret_cast<const float4*>(W) + h * (FF * 2);
#pragma unroll 8
    for (int f = 0; f < FF; f++) {
        float x = sH[lane * 129 + f];                 // conflict-free scalar LDS
        float4 w0 = __ldg(Wp + f * 2);                // uniform per-warp broadcast
        float4 w1 = __ldg(Wp + f * 2 + 1);
        hw[0] += x * w0.x; hw[1] += x * w0.y; hw[2] += x * w0.z; hw[3] += x * w0.w;
        hw[4] += x * w1.x; hw[5] += x * w1.y; hw[6] += x * w1.z; hw[7] += x * w1.w;
    }

    float el = 0.f, er = 0.f;
#pragma unroll
    for (int u = 0; u < 8; u++) {
        el += hw[u] * __ldg(al + h * 8 + u);
        er += hw[u] * __ldg(ar + h * 8 + u);
    }
    const float s = expf(er);
    g_el[h * NN + n] = el;

#pragma unroll
    for (int u = 0; u < 8; u++) {
        float v = s * hw[u];
        __nv_bfloat16 hi = __float2bfloat16(v);
        float lo = v - __bfloat162float(hi);
        g_Xp[(h * 8 + u) * NN + n] = hi;                      // coalesced (lane = n)
        g_Xp[(80 + h * 8 + u) * NN + n] = __float2bfloat16(lo);
    }
    {
        __nv_bfloat16 shi = __float2bfloat16(s);
        float slo = s - __bfloat162float(shi);
        g_Xp[(64 + h) * NN + n] = shi;
        g_Xp[(144 + h) * NN + n] = __float2bfloat16(slo);
    }
    if (h == 0) {
        const __nv_bfloat16 one = __float2bfloat16(1.0f);
        const __nv_bfloat16 zero = __float2bfloat16(0.0f);
        g_Xp[72 * NN + n] = one;        // degree column
        g_Xp[152 * NN + n] = zero;
#pragma unroll
        for (int c2 = 73; c2 < 80; c2++) {
            g_Xp[c2 * NN + n] = zero;
            g_Xp[(c2 + 80) * NN + n] = zero;
        }
    }
}

// ---------------- GEMM: A[4096x4096] @ Xp[4096x160], K-split partials ----------------
// grid (32, 4): x = M-tile, y = K-split. 256 threads = 8 warps (2 M x 4 N).
// A: LDG->reg (2 chunks ahead) -> bf16 cvt -> STS, double-buffered.
// B: cp.async 8B into 4-stage ring, issued 2 chunks ahead.
__global__ __launch_bounds__(256, 1) void gat_gemm(const float* __restrict__ A)
{
    extern __shared__ __align__(16) char smem[];
    __nv_bfloat16* Asm = reinterpret_cast<__nv_bfloat16*>(smem);               // 2 stages
    const uint32_t sbB = smem_u32(smem) + BBASE;                               // B ring base

    const int tid = threadIdx.x;
    const int lane = tid & 31, wid = tid >> 5;
    const int g = lane >> 2, tg = lane & 3;
    const int wm = wid & 1;        // 0..1  (rows 64*wm)
    const int wn = wid >> 1;       // 0..3  (cols 40*wn)
    const int rowBase = blockIdx.x * MT;
    const int kBase = blockIdx.y * KPC;

    // A loader: 2 threads per row, 16 floats each
    const int arow = tid >> 1;            // 0..127
    const int acol = (tid & 1) * 16;      // 0 or 16
    const float* Aptr = A + (size_t)(rowBase + arow) * NN + kBase + acol;

    // B loader: 5 x 8B per thread per chunk
    // idx = tid + it*256 (it<5): cc = idx>>3 (0..159), kp = (idx&7)*4
    float4 pa0[4], pa1[4];

    // ---- prologue ----
#pragma unroll
    for (int j = 0; j < 4; j++) pa0[j] = *reinterpret_cast<const float4*>(Aptr + j * 4);
#pragma unroll
    for (int j = 0; j < 4; j++) pa1[j] = *reinterpret_cast<const float4*>(Aptr + KC + j * 4);
#pragma unroll
    for (int c = 0; c < 2; c++) {
#pragma unroll
        for (int it = 0; it < 5; it++) {
            int idx = tid + it * 256;
            int cc = idx >> 3, kp = (idx & 7) * 4;
            cpasync8(sbB + c * BSTG + (cc * SSTR + kp) * 2,
                     g_Xp + (size_t)cc * NN + kBase + c * KC + kp);
        }
        asm volatile("cp.async.commit_group;" ::: "memory");
    }

    float acc[4][5][4];
#pragma unroll
    for (int mt = 0; mt < 4; mt++)
#pragma unroll
        for (int nt = 0; nt < 5; nt++)
#pragma unroll
            for (int q = 0; q < 4; q++) acc[mt][nt][q] = 0.f;

#pragma unroll 1
    for (int c = 0; c < NCHUNK; c++) {
        float4* pa = (c & 1) ? pa1 : pa0;
        __nv_bfloat16* as = Asm + (c & 1) * (MT * SSTR);
        const uint32_t bsAddr = sbB + (c & 3) * BSTG;
        const __nv_bfloat16* bs = reinterpret_cast<const __nv_bfloat16*>(
            smem + BBASE + (c & 3) * BSTG);

        // ---- STS A(c): fp32 regs -> bf16 smem ----
#pragma unroll
        for (int j = 0; j < 4; j++) {
            __nv_bfloat162 p0 = __floats2bfloat162_rn(pa[j].x, pa[j].y);
            __nv_bfloat162 p1 = __floats2bfloat162_rn(pa[j].z, pa[j].w);
            uint2 v;
            v.x = *reinterpret_cast<uint32_t*>(&p0);
            v.y = *reinterpret_cast<uint32_t*>(&p1);
            *reinterpret_cast<uint2*>(as + arow * SSTR + acol + j * 4) = v;
        }
        // ---- LDG A(c+2) into the bank just freed ----
        if (c + 2 < NCHUNK) {
#pragma unroll
            for (int j = 0; j < 4; j++)
                pa[j] = *reinterpret_cast<const float4*>(Aptr + (c + 2) * KC + j * 4);
        }
        // ---- cp.async B(c+2) into ring stage (c+2)&3 ----
        if (c + 2 < NCHUNK) {
#pragma unroll
            for (int it = 0; it < 5; it++) {
                int idx = tid + it * 256;
                int cc = idx >> 3, kp = (idx & 7) * 4;
                cpasync8(sbB + ((c + 2) & 3) * BSTG + (cc * SSTR + kp) * 2,
                         g_Xp + (size_t)cc * NN + kBase + (c + 2) * KC + kp);
            }
            asm volatile("cp.async.commit_group;" ::: "memory");
        }
        // ---- drain to guarantee B(c) landed, then make visible CTA-wide ----
        if (c + 2 < NCHUNK)      asm volatile("cp.async.wait_group 2;" ::: "memory");
        else if (c + 1 < NCHUNK) asm volatile("cp.async.wait_group 1;" ::: "memory");
        else                     asm volatile("cp.async.wait_group 0;" ::: "memory");
        __syncthreads();

        // ---- MMA over staged chunk (2 x k16) ----
#pragma unroll
        for (int k16 = 0; k16 < 2; k16++) {
            const int kb = k16 * 16;
            uint32_t a[4][4];
#pragma unroll
            for (int mt = 0; mt < 4; mt++) {
                int r = wm * 64 + mt * 16 + g;
                a[mt][0] = *reinterpret_cast<const uint32_t*>(as + r * SSTR + kb + tg * 2);
                a[mt][1] = *reinterpret_cast<const uint32_t*>(as + (r + 8) * SSTR + kb + tg * 2);
                a[mt][2] = *reinterpret_cast<const uint32_t*>(as + r * SSTR + kb + 8 + tg * 2);
                a[mt][3] = *reinterpret_cast<const uint32_t*>(as + (r + 8) * SSTR + kb + 8 + tg * 2);
            }
#pragma unroll
            for (int nt = 0; nt < 5; nt++) {
                int col = wn * 40 + nt * 8 + g;
                uint32_t b0 = *reinterpret_cast<const uint32_t*>(bs + col * SSTR + kb + tg * 2);
                uint32_t b1 = *reinterpret_cast<const uint32_t*>(bs + col * SSTR + kb + 8 + tg * 2);
#pragma unroll
                for (int mt = 0; mt < 4; mt++)
                    mma16816v(acc[mt][nt], a[mt][0], a[mt][1], a[mt][2], a[mt][3], b0, b1);
            }
        }
        (void)bsAddr;
    }

    // ---- store partials to scratch ----
    float* pp = &g_part[blockIdx.y][0][0];
#pragma unroll
    for (int mt = 0; mt < 4; mt++) {
#pragma unroll
        for (int nt = 0; nt < 5; nt++) {
            int r = rowBase + wm * 64 + mt * 16 + g;
            int col = wn * 40 + nt * 8 + tg * 2;
            float2 v0 = make_float2(acc[mt][nt][0], acc[mt][nt][1]);
            float2 v1 = make_float2(acc[mt][nt][2], acc[mt][nt][3]);
            *reinterpret_cast<float2*>(pp + (size_t)r * NCOL + col) = v0;
            *reinterpret_cast<float2*>(pp + (size_t)(r + 8) * NCOL + col) = v1;
        }
    }
}

// ---------------- epilogue: reduce K-splits + normalize + elu ----------------
__global__ __launch_bounds__(256) void gat_epilogue(float* __restrict__ out)
{
    const int t = blockIdx.x * 256 + threadIdx.x;
    const int n = t >> 3, h = t & 7;

    float4 hi0 = make_float4(0, 0, 0, 0), hi1 = hi0, lo0 = hi0, lo1 = hi0;
    float sden = 0.f, deg = 0.f;
#pragma unroll
    for (int s = 0; s < KSPLIT; s++) {
        const float* base = &g_part[s][n][0];
        float4 a0 = *reinterpret_cast<const float4*>(base + h * 8);
        float4 a1 = *reinterpret_cast<const float4*>(base + h * 8 + 4);
        float4 b0 = *reinterpret_cast<const float4*>(base + 80 + h * 8);
        float4 b1 = *reinterpret_cast<const float4*>(base + 80 + h * 8 + 4);
        hi0.x += a0.x; hi0.y += a0.y; hi0.z += a0.z; hi0.w += a0.w;
        hi1.x += a1.x; hi1.y += a1.y; hi1.z += a1.z; hi1.w += a1.w;
        lo0.x += b0.x; lo0.y += b0.y; lo0.z += b0.z; lo0.w += b0.w;
        lo1.x += b1.x; lo1.y += b1.y; lo1.z += b1.z; lo1.w += b1.w;
        sden += base[64 + h] + base[144 + h];
        deg  += base[72] + base[152];
    }

    const float e = expf(g_el[h * NN + n]);
    const float denom = (float)NN - deg + e * sden;
    const float r = e / denom;

    float v[8];
    v[0] = (hi0.x + lo0.x) * r; v[1] = (hi0.y + lo0.y) * r;
    v[2] = (hi0.z + lo0.z) * r; v[3] = (hi0.w + lo0.w) * r;
    v[4] = (hi1.x + lo1.x) * r; v[5] = (hi1.y + lo1.y) * r;
    v[6] = (hi1.z + lo1.z) * r; v[7] = (hi1.w + lo1.w) * r;

    float4 o0, o1;
    o0.x = v[0] > 0.f ? v[0] : expm1f(v[0]);
    o0.y = v[1] > 0.f ? v[1] : expm1f(v[1]);
    o0.z = v[2] > 0.f ? v[2] : expm1f(v[2]);
    o0.w = v[3] > 0.f ? v[3] : expm1f(v[3]);
    o1.x = v[4] > 0.f ? v[4] : expm1f(v[4]);
    o1.y = v[5] > 0.f ? v[5] : expm1f(v[5]);
    o1.z = v[6] > 0.f ? v[6] : expm1f(v[6]);
    o1.w = v[7] > 0.f ? v[7] : expm1f(v[7]);

    float4* op = reinterpret_cast<float4*>(out + (size_t)n * (HEADS * UU) + h * 8);
    op[0] = o0;
    op[1] = o1;
}

// ---------------- launcher ----------------
extern "C" void kernel_launch(void* const* d_in, const int* in_sizes, int n_in,
                              void* d_out, int out_size)
{
    (void)in_sizes; (void)n_in; (void)out_size;
    const float* A  = (const float*)d_in[0];
    const float* H  = (const float*)d_in[1];
    const float* W  = (const float*)d_in[2];
    const float* al = (const float*)d_in[3];
    const float* ar = (const float*)d_in[4];
    float* out = (float*)d_out;

    cudaFuncSetAttribute(gat_gemm, cudaFuncAttributeMaxDynamicSharedMemorySize, GEMM_SMEM);

    gat_build<<<NN / 32, 256>>>(H, W, al, ar);
    dim3 gg(NN / MT, KSPLIT);
    gat_gemm<<<gg, 256, GEMM_SMEM>>>(A);
    gat_epilogue<<<NN * HEADS / 256, 256>>>(out);
}

// round 10
// speedup vs baseline: 1.0882x; 1.0882x over previous
#include <cuda_runtime.h>
#include <cuda_bf16.h>
#include <cstdint>

// Problem constants (fixed shapes)
#define NN 4096
#define FF 128
#define HEADS 8
#define UU 8
#define NCOL 160        // 80 hi cols + 80 lo cols
#define MT 128          // GEMM M-tile
#define KSPLIT 4        // K-splits
#define KPC 1024        // K per CTA
#define KC 32           // K chunk per pipeline stage
#define NCHUNK (KPC / KC)   // 32
#define SSTR 40         // smem K-stride (elements)

// ---------------- device scratch (no allocations allowed) ----------------
__device__ __align__(128) __nv_bfloat16 g_Xp[NCOL * NN];   // [col][node]
__device__ __align__(128) float g_el[HEADS * NN];
__device__ __align__(128) float g_part[KSPLIT][NN][NCOL];  // 10.5 MB partials

// ---------------- prep kernel: build Xp and e_l ----------------
// 512 threads = 16 warps = (fs in 0..1) x (head 0..7); lane = node (32/block).
// W staged in smem h-major -> in-loop W reads are warp-uniform broadcasts.
#define BUILD_SMEM ((32 * 129 + HEADS * FF * UU + 2 * 2048) * 4)  // 65664 B
__global__ __launch_bounds__(512) void gat_build(
    const float* __restrict__ H, const float* __restrict__ W,
    const float* __restrict__ al, const float* __restrict__ ar)
{
    extern __shared__ float sm[];
    float* sH = sm;                        // [n*129 + f], conflict-free scalar LDS
    float* sW = sH + 32 * 129;             // [h*1024 + f*8 + u], broadcast reads
    float* sP = sW + HEADS * FF * UU;      // [fs*2048 + h*256 + n*8 + u]

    const int tid = threadIdx.x;
    const int lane = tid & 31;
    const int w = tid >> 5;
    const int fs = w >> 3;        // 0..1
    const int h = w & 7;          // 0..7
    const int nodeBase = blockIdx.x * 32;

    for (int i = tid; i < HEADS * FF * UU; i += 512) sW[i] = W[i];
    for (int i = tid; i < 32 * FF; i += 512) {
        int nn = i >> 7, f = i & 127;
        sH[nn * 129 + f] = H[(size_t)(nodeBase + nn) * FF + f];
    }
    __syncthreads();

    // ---- partial HW over 64 features ----
    float hw[8];
#pragma unroll
    for (int u = 0; u < 8; u++) hw[u] = 0.f;
    const int f0 = fs * 64;
#pragma unroll
    for (int ff = 0; ff < 64; ff++) {
        const int f = f0 + ff;
        float x = sH[lane * 129 + f];
        float4 w0 = *reinterpret_cast<const float4*>(sW + h * 1024 + f * 8);
        float4 w1 = *reinterpret_cast<const float4*>(sW + h * 1024 + f * 8 + 4);
        hw[0] += x * w0.x; hw[1] += x * w0.y; hw[2] += x * w0.z; hw[3] += x * w0.w;
        hw[4] += x * w1.x; hw[5] += x * w1.y; hw[6] += x * w1.z; hw[7] += x * w1.w;
    }
    float* pdst = sP + fs * 2048 + h * 256 + lane * 8;
    *reinterpret_cast<float4*>(pdst)     = make_float4(hw[0], hw[1], hw[2], hw[3]);
    *reinterpret_cast<float4*>(pdst + 4) = make_float4(hw[4], hw[5], hw[6], hw[7]);
    __syncthreads();

    // ---- reduce + finalize (first 8 warps; warp = head, lane = node) ----
    if (w < 8) {
        const int hh = w;
        const int n = nodeBase + lane;
        const float* p0 = sP + hh * 256 + lane * 8;
        const float* p1 = p0 + 2048;
        float v[8];
#pragma unroll
        for (int u = 0; u < 8; u++) v[u] = p0[u] + p1[u];

        float el = 0.f, er = 0.f;
#pragma unroll
        for (int u = 0; u < 8; u++) {
            el += v[u] * __ldg(al + hh * 8 + u);
            er += v[u] * __ldg(ar + hh * 8 + u);
        }
        const float s = expf(er);
        g_el[hh * NN + n] = el;

#pragma unroll
        for (int u = 0; u < 8; u++) {
            float t = s * v[u];
            __nv_bfloat16 hi = __float2bfloat16(t);
            float lo = t - __bfloat162float(hi);
            g_Xp[(hh * 8 + u) * NN + n] = hi;                    // coalesced (lane = n)
            g_Xp[(80 + hh * 8 + u) * NN + n] = __float2bfloat16(lo);
        }
        {
            __nv_bfloat16 shi = __float2bfloat16(s);
            float slo = s - __bfloat162float(shi);
            g_Xp[(64 + hh) * NN + n] = shi;
            g_Xp[(144 + hh) * NN + n] = __float2bfloat16(slo);
        }
        if (hh == 0) {
            const __nv_bfloat16 one = __float2bfloat16(1.0f);
            const __nv_bfloat16 zero = __float2bfloat16(0.0f);
            g_Xp[72 * NN + n] = one;       // degree column
            g_Xp[152 * NN + n] = zero;
#pragma unroll
            for (int c2 = 73; c2 < 80; c2++) {
                g_Xp[c2 * NN + n] = zero;
                g_Xp[(c2 + 80) * NN + n] = zero;
            }
        }
    }
}

// ---------------- bf16 mma helper ----------------
__device__ __forceinline__ void mma16816v(float c[4], uint32_t a0, uint32_t a1,
                                          uint32_t a2, uint32_t a3,
                                          uint32_t b0, uint32_t b1)
{
    asm volatile(
        "mma.sync.aligned.m16n8k16.row.col.f32.bf16.bf16.f32 "
        "{%0,%1,%2,%3}, {%4,%5,%6,%7}, {%8,%9}, {%0,%1,%2,%3};\n"
        : "+f"(c[0]), "+f"(c[1]), "+f"(c[2]), "+f"(c[3])
        : "r"(a0), "r"(a1), "r"(a2), "r"(a3), "r"(b0), "r"(b1));
}

// ---------------- GEMM: A[4096x4096] @ Xp[4096x160]  (R2-proven version) ----------------
// grid (32, 4): x = M-tile, y = K-split. 256 threads = 8 warps (2 M x 4 N).
__global__ __launch_bounds__(256, 1) void gat_gemm(const float* __restrict__ A)
{
    __shared__ __align__(16) __nv_bfloat16 As[2][MT * SSTR];    // 2 x 10 KB
    __shared__ __align__(16) __nv_bfloat16 Bs[2][NCOL * SSTR];  // 2 x 12.5 KB

    const int tid = threadIdx.x;
    const int lane = tid & 31, wid = tid >> 5;
    const int g = lane >> 2, tg = lane & 3;
    const int wm = wid & 1;        // 0..1  (rows 64*wm)
    const int wn = wid >> 1;       // 0..3  (cols 40*wn)
    const int rowBase = blockIdx.x * MT;
    const int kBase = blockIdx.y * KPC;

    // A loader: 4 threads per row, 8 floats each (R2-proven mapping)
    const int arow = tid >> 2;            // 0..63?? -> need 128 rows: tid>>2 gives 0..63
    // NOTE: 256 threads / 4 per row = 64 rows only; use 2 threads per row, 16 floats:
    const int arow2 = tid >> 1;           // 0..127
    const int acol2 = (tid & 1) * 16;     // 0 or 16
    const float* Aptr = A + (size_t)(rowBase + arow2) * NN + kBase + acol2;

    // B loader (R2-exact): uint2 pb[5]; idx = tid + it*256; cc = idx>>3 (0..159), ke = (idx&7)*4
    float4 pa0[4], pa1[4];
    uint2 pb[5];

#pragma unroll
    for (int j = 0; j < 4; j++) pa0[j] = *reinterpret_cast<const float4*>(Aptr + j * 4);
#pragma unroll
    for (int j = 0; j < 4; j++) pa1[j] = *reinterpret_cast<const float4*>(Aptr + KC + j * 4);
#pragma unroll
    for (int it = 0; it < 5; it++) {
        int idx = tid + it * 256;
        int cc = idx >> 3, ke = (idx & 7) * 4;
        pb[it] = *reinterpret_cast<const uint2*>(g_Xp + (size_t)cc * NN + kBase + ke);
    }

    float acc[4][5][4];
#pragma unroll
    for (int mt = 0; mt < 4; mt++)
#pragma unroll
        for (int nt = 0; nt < 5; nt++)
#pragma unroll
            for (int q = 0; q < 4; q++) acc[mt][nt][q] = 0.f;

#pragma unroll 1
    for (int c = 0; c < NCHUNK; c++) {
        float4* pa = (c & 1) ? pa1 : pa0;
        __nv_bfloat16* as = As[c & 1];
        __nv_bfloat16* bs = Bs[c & 1];

        // ---- STS A (fp32 regs -> bf16 smem) ----
#pragma unroll
        for (int j = 0; j < 4; j++) {
            __nv_bfloat162 p0 = __floats2bfloat162_rn(pa[j].x, pa[j].y);
            __nv_bfloat162 p1 = __floats2bfloat162_rn(pa[j].z, pa[j].w);
            uint2 v;
            v.x = *reinterpret_cast<uint32_t*>(&p0);
            v.y = *reinterpret_cast<uint32_t*>(&p1);
            *reinterpret_cast<uint2*>(as + arow2 * SSTR + acol2 + j * 4) = v;
        }
        // ---- STS B (full 160 cols x 32 k) ----
#pragma unroll
        for (int it = 0; it < 5; it++) {
            int idx = tid + it * 256;
            int cc = idx >> 3, ke = (idx & 7) * 4;
            *reinterpret_cast<uint2*>(bs + cc * SSTR + ke) = pb[it];
        }
        // ---- prefetch: A 2 ahead, B 1 ahead ----
        if (c + 2 < NCHUNK) {
#pragma unroll
            for (int j = 0; j < 4; j++)
                pa[j] = *reinterpret_cast<const float4*>(Aptr + (c + 2) * KC + j * 4);
        }
        if (c + 1 < NCHUNK) {
#pragma unroll
            for (int it = 0; it < 5; it++) {
                int idx = tid + it * 256;
                int cc = idx >> 3, ke = (idx & 7) * 4;
                pb[it] = *reinterpret_cast<const uint2*>(
                    g_Xp + (size_t)cc * NN + kBase + (c + 1) * KC + ke);
            }
        }
        __syncthreads();

        // ---- MMA over staged chunk (2 x k16) ----
#pragma unroll
        for (int k16 = 0; k16 < 2; k16++) {
            const int kb = k16 * 16;
            uint32_t a[4][4];
#pragma unroll
            for (int mt = 0; mt < 4; mt++) {
                int r = wm * 64 + mt * 16 + g;
                a[mt][0] = *reinterpret_cast<const uint32_t*>(as + r * SSTR + kb + tg * 2);
                a[mt][1] = *reinterpret_cast<const uint32_t*>(as + (r + 8) * SSTR + kb + tg * 2);
                a[mt][2] = *reinterpret_cast<const uint32_t*>(as + r * SSTR + kb + 8 + tg * 2);
                a[mt][3] = *reinterpret_cast<const uint32_t*>(as + (r + 8) * SSTR + kb + 8 + tg * 2);
            }
#pragma unroll
            for (int nt = 0; nt < 5; nt++) {
                int col = wn * 40 + nt * 8 + g;
                uint32_t b0 = *reinterpret_cast<const uint32_t*>(bs + col * SSTR + kb + tg * 2);
                uint32_t b1 = *reinterpret_cast<const uint32_t*>(bs + col * SSTR + kb + 8 + tg * 2);
#pragma unroll
                for (int mt = 0; mt < 4; mt++)
                    mma16816v(acc[mt][nt], a[mt][0], a[mt][1], a[mt][2], a[mt][3], b0, b1);
            }
        }
        __syncthreads();
    }
    (void)arow;

    // ---- store partials to scratch ----
    float* pp = &g_part[blockIdx.y][0][0];
#pragma unroll
    for (int mt = 0; mt < 4; mt++) {
#pragma unroll
        for (int nt = 0; nt < 5; nt++) {
            int r = rowBase + wm * 64 + mt * 16 + g;
            int col = wn * 40 + nt * 8 + tg * 2;
            float2 v0 = make_float2(acc[mt][nt][0], acc[mt][nt][1]);
            float2 v1 = make_float2(acc[mt][nt][2], acc[mt][nt][3]);
            *reinterpret_cast<float2*>(pp + (size_t)r * NCOL + col) = v0;
            *reinterpret_cast<float2*>(pp + (size_t)(r + 8) * NCOL + col) = v1;
        }
    }
}

// ---------------- epilogue: reduce K-splits + normalize + elu ----------------
__global__ __launch_bounds__(256) void gat_epilogue(float* __restrict__ out)
{
    const int t = blockIdx.x * 256 + threadIdx.x;
    const int n = t >> 3, h = t & 7;

    float4 hi0 = make_float4(0, 0, 0, 0), hi1 = hi0, lo0 = hi0, lo1 = hi0;
    float sden = 0.f, deg = 0.f;
#pragma unroll
    for (int s = 0; s < KSPLIT; s++) {
        const float* base = &g_part[s][n][0];
        float4 a0 = *reinterpret_cast<const float4*>(base + h * 8);
        float4 a1 = *reinterpret_cast<const float4*>(base + h * 8 + 4);
        float4 b0 = *reinterpret_cast<const float4*>(base + 80 + h * 8);
        float4 b1 = *reinterpret_cast<const float4*>(base + 80 + h * 8 + 4);
        hi0.x += a0.x; hi0.y += a0.y; hi0.z += a0.z; hi0.w += a0.w;
        hi1.x += a1.x; hi1.y += a1.y; hi1.z += a1.z; hi1.w += a1.w;
        lo0.x += b0.x; lo0.y += b0.y; lo0.z += b0.z; lo0.w += b0.w;
        lo1.x += b1.x; lo1.y += b1.y; lo1.z += b1.z; lo1.w += b1.w;
        sden += base[64 + h] + base[144 + h];
        deg  += base[72] + base[152];
    }

    const float e = expf(g_el[h * NN + n]);
    const float denom = (float)NN - deg + e * sden;
    const float r = e / denom;

    float v[8];
    v[0] = (hi0.x + lo0.x) * r; v[1] = (hi0.y + lo0.y) * r;
    v[2] = (hi0.z + lo0.z) * r; v[3] = (hi0.w + lo0.w) * r;
    v[4] = (hi1.x + lo1.x) * r; v[5] = (hi1.y + lo1.y) * r;
    v[6] = (hi1.z + lo1.z) * r; v[7] = (hi1.w + lo1.w) * r;

    float4 o0, o1;
    o0.x = v[0] > 0.f ? v[0] : expm1f(v[0]);
    o0.y = v[1] > 0.f ? v[1] : expm1f(v[1]);
    o0.z = v[2] > 0.f ? v[2] : expm1f(v[2]);
    o0.w = v[3] > 0.f ? v[3] : expm1f(v[3]);
    o1.x = v[4] > 0.f ? v[4] : expm1f(v[4]);
    o1.y = v[5] > 0.f ? v[5] : expm1f(v[5]);
    o1.z = v[6] > 0.f ? v[6] : expm1f(v[6]);
    o1.w = v[7] > 0.f ? v[7] : expm1f(v[7]);

    float4* op = reinterpret_cast<float4*>(out + (size_t)n * (HEADS * UU) + h * 8);
    op[0] = o0;
    op[1] = o1;
}

// ---------------- launcher ----------------
extern "C" void kernel_launch(void* const* d_in, const int* in_sizes, int n_in,
                              void* d_out, int out_size)
{
    (void)in_sizes; (void)n_in; (void)out_size;
    const float* A  = (const float*)d_in[0];
    const float* H  = (const float*)d_in[1];
    const float* W  = (const float*)d_in[2];
    const float* al = (const float*)d_in[3];
    const float* ar = (const float*)d_in[4];
    float* out = (float*)d_out;

    cudaFuncSetAttribute(gat_build, cudaFuncAttributeMaxDynamicSharedMemorySize, BUILD_SMEM);

    gat_build<<<NN / 32, 512, BUILD_SMEM>>>(H, W, al, ar);
    dim3 gg(NN / MT, KSPLIT);
    gat_gemm<<<gg, 256>>>(A);
    gat_epilogue<<<NN * HEADS / 256, 256>>>(out);
}

// round 11
// speedup vs baseline: 1.3673x; 1.2565x over previous
#include <cuda_runtime.h>
#include <cuda_bf16.h>
#include <cstdint>

// Problem constants (fixed shapes)
#define NN 4096
#define FF 128
#define HEADS 8
#define UU 8
#define NCOL 160        // 80 hi cols + 80 lo cols
#define MT 128          // GEMM M-tile
#define KSPLIT 4        // K-splits
#define KPC 1024        // K per CTA
#define KC 32           // K chunk per pipeline stage
#define NCHUNK (KPC / KC)   // 32
#define SSTR 40         // smem K-stride (elements)

// ---------------- device scratch (no allocations allowed) ----------------
__device__ __align__(128) __nv_bfloat16 g_Xp[NCOL * NN];   // [col][node]
__device__ __align__(128) float g_el[HEADS * NN];
__device__ __align__(128) float g_part[KSPLIT][NN][NCOL];  // 10.5 MB partials

// ---------------- prep kernel: build Xp and e_l ----------------
// 512 threads = 16 warps = (fs in 0..1) x (head 0..7); lane = node (32/block).
// W staged in smem h-major -> warp-uniform broadcast LDS.
// f processed in groups of 8 with ALL loads issued before the FFMAs (forced ILP).
#define BUILD_SMEM ((32 * 129 + HEADS * FF * UU + 2 * 2048) * 4)  // 65664 B
__global__ __launch_bounds__(512, 1) void gat_build(
    const float* __restrict__ H, const float* __restrict__ W,
    const float* __restrict__ al, const float* __restrict__ ar)
{
    extern __shared__ float sm[];
    float* sH = sm;                        // [n*129 + f]
    float* sW = sH + 32 * 129;             // [h*1024 + f*8 + u]
    float* sP = sW + HEADS * FF * UU;      // [fs*2048 + h*256 + n*8 + u]

    const int tid = threadIdx.x;
    const int lane = tid & 31;
    const int w = tid >> 5;
    const int fs = w >> 3;        // 0..1
    const int h = w & 7;          // 0..7
    const int nodeBase = blockIdx.x * 32;

    for (int i = tid; i < HEADS * FF * UU; i += 512) sW[i] = W[i];
    for (int i = tid; i < 32 * FF; i += 512) {
        int nn = i >> 7, f = i & 127;
        sH[nn * 129 + f] = H[(size_t)(nodeBase + nn) * FF + f];
    }
    __syncthreads();

    // ---- partial HW over 64 features, groups of 8 with batched loads ----
    float hw[8];
#pragma unroll
    for (int u = 0; u < 8; u++) hw[u] = 0.f;
    const int f0 = fs * 64;
    const float* xrow = sH + lane * 129 + f0;
    const float* wrow = sW + h * 1024 + f0 * 8;

#pragma unroll
    for (int fg = 0; fg < 8; fg++) {
        float x[8];
        float4 wv[16];
#pragma unroll
        for (int e = 0; e < 8; e++) x[e] = xrow[fg * 8 + e];
#pragma unroll
        for (int e = 0; e < 8; e++) {
            wv[2 * e]     = *reinterpret_cast<const float4*>(wrow + (fg * 8 + e) * 8);
            wv[2 * e + 1] = *reinterpret_cast<const float4*>(wrow + (fg * 8 + e) * 8 + 4);
        }
#pragma unroll
        for (int e = 0; e < 8; e++) {
            float a = x[e];
            float4 w0 = wv[2 * e], w1 = wv[2 * e + 1];
            hw[0] += a * w0.x; hw[1] += a * w0.y; hw[2] += a * w0.z; hw[3] += a * w0.w;
            hw[4] += a * w1.x; hw[5] += a * w1.y; hw[6] += a * w1.z; hw[7] += a * w1.w;
        }
    }
    float* pdst = sP + fs * 2048 + h * 256 + lane * 8;
    *reinterpret_cast<float4*>(pdst)     = make_float4(hw[0], hw[1], hw[2], hw[3]);
    *reinterpret_cast<float4*>(pdst + 4) = make_float4(hw[4], hw[5], hw[6], hw[7]);
    __syncthreads();

    // ---- reduce + finalize (first 8 warps; warp = head, lane = node) ----
    if (w < 8) {
        const int hh = w;
        const int n = nodeBase + lane;
        const float* p0 = sP + hh * 256 + lane * 8;
        const float* p1 = p0 + 2048;
        float v[8];
#pragma unroll
        for (int u = 0; u < 8; u++) v[u] = p0[u] + p1[u];

        float el = 0.f, er = 0.f;
#pragma unroll
        for (int u = 0; u < 8; u++) {
            el += v[u] * __ldg(al + hh * 8 + u);
            er += v[u] * __ldg(ar + hh * 8 + u);
        }
        const float s = expf(er);
        g_el[hh * NN + n] = el;

#pragma unroll
        for (int u = 0; u < 8; u++) {
            float t = s * v[u];
            __nv_bfloat16 hi = __float2bfloat16(t);
            float lo = t - __bfloat162float(hi);
            g_Xp[(hh * 8 + u) * NN + n] = hi;
            g_Xp[(80 + hh * 8 + u) * NN + n] = __float2bfloat16(lo);
        }
        {
            __nv_bfloat16 shi = __float2bfloat16(s);
            float slo = s - __bfloat162float(shi);
            g_Xp[(64 + hh) * NN + n] = shi;
            g_Xp[(144 + hh) * NN + n] = __float2bfloat16(slo);
        }
        if (hh == 0) {
            const __nv_bfloat16 one = __float2bfloat16(1.0f);
            const __nv_bfloat16 zero = __float2bfloat16(0.0f);
            g_Xp[72 * NN + n] = one;       // degree column
            g_Xp[152 * NN + n] = zero;
#pragma unroll
            for (int c2 = 73; c2 < 80; c2++) {
                g_Xp[c2 * NN + n] = zero;
                g_Xp[(c2 + 80) * NN + n] = zero;
            }
        }
    }
}

// ---------------- bf16 mma helper ----------------
__device__ __forceinline__ void mma16816v(float c[4], uint32_t a0, uint32_t a1,
                                          uint32_t a2, uint32_t a3,
                                          uint32_t b0, uint32_t b1)
{
    asm volatile(
        "mma.sync.aligned.m16n8k16.row.col.f32.bf16.bf16.f32 "
        "{%0,%1,%2,%3}, {%4,%5,%6,%7}, {%8,%9}, {%0,%1,%2,%3};\n"
        : "+f"(c[0]), "+f"(c[1]), "+f"(c[2]), "+f"(c[3])
        : "r"(a0), "r"(a1), "r"(a2), "r"(a3), "r"(b0), "r"(b1));
}

// ---------------- GEMM: A[4096x4096] @ Xp[4096x160]  (R2-proven, verbatim) ----------------
// grid (32, 4): x = M-tile, y = K-split. 256 threads = 8 warps (2 M x 4 N).
struct GemmCtx {
    const float* Aptr;
    int tid, g, tg, wm, wn;
    int kBase0;
};

__device__ __forceinline__ void gemm_step(
    const GemmCtx& cx, int c,
    __nv_bfloat16* __restrict__ as, __nv_bfloat16* __restrict__ bs,
    float4 (&pac)[4], uint2 (&pb)[5], float (&acc)[4][5][4])
{
    const int tid = cx.tid;
    const int arow = tid >> 1;
    const int akh = (tid & 1) * 16;

    // ---- STS A (fp32 regs -> bf16 smem) ----
#pragma unroll
    for (int j = 0; j < 4; j++) {
        __nv_bfloat162 p0 = __floats2bfloat162_rn(pac[j].x, pac[j].y);
        __nv_bfloat162 p1 = __floats2bfloat162_rn(pac[j].z, pac[j].w);
        uint2 v;
        v.x = *reinterpret_cast<uint32_t*>(&p0);
        v.y = *reinterpret_cast<uint32_t*>(&p1);
        *reinterpret_cast<uint2*>(as + arow * SSTR + akh + j * 4) = v;
    }
    // ---- STS B ----
#pragma unroll
    for (int it = 0; it < 5; it++) {
        int idx = tid + it * 256;
        int cc = idx >> 3, ke = (idx & 7) * 4;
        *reinterpret_cast<uint2*>(bs + cc * SSTR + ke) = pb[it];
    }
    // ---- LDG next: A 2 chunks ahead, B 1 chunk ahead ----
    if (c + 2 < NCHUNK) {
#pragma unroll
        for (int j = 0; j < 4; j++)
            pac[j] = *reinterpret_cast<const float4*>(cx.Aptr + (c + 2) * KC + j * 4);
    }
    if (c + 1 < NCHUNK) {
#pragma unroll
        for (int it = 0; it < 5; it++) {
            int idx = tid + it * 256;
            int cc = idx >> 3, ke = (idx & 7) * 4;
            pb[it] = *reinterpret_cast<const uint2*>(
                g_Xp + (size_t)cc * NN + cx.kBase0 + (c + 1) * KC + ke);
        }
    }
    __syncthreads();

    // ---- MMA over staged chunk (2 x k16) ----
#pragma unroll
    for (int k16 = 0; k16 < 2; k16++) {
        const int kb = k16 * 16;
        uint32_t a[4][4];
#pragma unroll
        for (int mt = 0; mt < 4; mt++) {
            int r = cx.wm * 64 + mt * 16 + cx.g;
            a[mt][0] = *reinterpret_cast<const uint32_t*>(as + r * SSTR + kb + cx.tg * 2);
            a[mt][1] = *reinterpret_cast<const uint32_t*>(as + (r + 8) * SSTR + kb + cx.tg * 2);
            a[mt][2] = *reinterpret_cast<const uint32_t*>(as + r * SSTR + kb + 8 + cx.tg * 2);
            a[mt][3] = *reinterpret_cast<const uint32_t*>(as + (r + 8) * SSTR + kb + 8 + cx.tg * 2);
        }
#pragma unroll
        for (int nt = 0; nt < 5; nt++) {
            int col = cx.wn * 40 + nt * 8 + cx.g;
            uint32_t b0 = *reinterpret_cast<const uint32_t*>(bs + col * SSTR + kb + cx.tg * 2);
            uint32_t b1 = *reinterpret_cast<const uint32_t*>(bs + col * SSTR + kb + 8 + cx.tg * 2);
#pragma unroll
            for (int mt = 0; mt < 4; mt++)
                mma16816v(acc[mt][nt], a[mt][0], a[mt][1], a[mt][2], a[mt][3], b0, b1);
        }
    }
}

__global__ __launch_bounds__(256, 1) void gat_gemm(const float* __restrict__ A)
{
    __shared__ __align__(16) __nv_bfloat16 As0[MT * SSTR];
    __shared__ __align__(16) __nv_bfloat16 As1[MT * SSTR];
    __shared__ __align__(16) __nv_bfloat16 Bs0[NCOL * SSTR];
    __shared__ __align__(16) __nv_bfloat16 Bs1[NCOL * SSTR];

    GemmCtx cx;
    const int tid = threadIdx.x;
    const int lane = tid & 31, wid = tid >> 5;
    cx.tid = tid;
    cx.g = lane >> 2; cx.tg = lane & 3;
    cx.wm = wid & 1;  cx.wn = wid >> 1;
    const int rowBase = blockIdx.x * MT;
    cx.kBase0 = blockIdx.y * KPC;

    const int arow = tid >> 1;
    const int akh = (tid & 1) * 16;
    cx.Aptr = A + (size_t)(rowBase + arow) * NN + cx.kBase0 + akh;

    float4 pa0[4], pa1[4];
    uint2 pb[5];
#pragma unroll
    for (int j = 0; j < 4; j++) pa0[j] = *reinterpret_cast<const float4*>(cx.Aptr + j * 4);
#pragma unroll
    for (int j = 0; j < 4; j++) pa1[j] = *reinterpret_cast<const float4*>(cx.Aptr + KC + j * 4);
#pragma unroll
    for (int it = 0; it < 5; it++) {
        int idx = tid + it * 256;
        int cc = idx >> 3, ke = (idx & 7) * 4;
        pb[it] = *reinterpret_cast<const uint2*>(g_Xp + (size_t)cc * NN + cx.kBase0 + ke);
    }

    float acc[4][5][4];
#pragma unroll
    for (int mt = 0; mt < 4; mt++)
#pragma unroll
        for (int nt = 0; nt < 5; nt++)
#pragma unroll
            for (int q = 0; q < 4; q++) acc[mt][nt][q] = 0.f;

    for (int ci = 0; ci < NCHUNK / 2; ci++) {
        gemm_step(cx, 2 * ci,     As0, Bs0, pa0, pb, acc);
        gemm_step(cx, 2 * ci + 1, As1, Bs1, pa1, pb, acc);
    }

    // ---- store partials to scratch ----
    float* pp = &g_part[blockIdx.y][0][0];
#pragma unroll
    for (int mt = 0; mt < 4; mt++) {
#pragma unroll
        for (int nt = 0; nt < 5; nt++) {
            int r = rowBase + cx.wm * 64 + mt * 16 + cx.g;
            int col = cx.wn * 40 + nt * 8 + cx.tg * 2;
            float2 v0 = make_float2(acc[mt][nt][0], acc[mt][nt][1]);
            float2 v1 = make_float2(acc[mt][nt][2], acc[mt][nt][3]);
            *reinterpret_cast<float2*>(pp + (size_t)r * NCOL + col) = v0;
            *reinterpret_cast<float2*>(pp + (size_t)(r + 8) * NCOL + col) = v1;
        }
    }
}

// ---------------- epilogue: reduce K-splits + normalize + elu ----------------
__global__ __launch_bounds__(256) void gat_epilogue(float* __restrict__ out)
{
    const int t = blockIdx.x * 256 + threadIdx.x;
    const int n = t >> 3, h = t & 7;

    float4 hi0 = make_float4(0, 0, 0, 0), hi1 = hi0, lo0 = hi0, lo1 = hi0;
    float sden = 0.f, deg = 0.f;
#pragma unroll
    for (int s = 0; s < KSPLIT; s++) {
        const float* base = &g_part[s][n][0];
        float4 a0 = *reinterpret_cast<const float4*>(base + h * 8);
        float4 a1 = *reinterpret_cast<const float4*>(base + h * 8 + 4);
        float4 b0 = *reinterpret_cast<const float4*>(base + 80 + h * 8);
        float4 b1 = *reinterpret_cast<const float4*>(base + 80 + h * 8 + 4);
        hi0.x += a0.x; hi0.y += a0.y; hi0.z += a0.z; hi0.w += a0.w;
        hi1.x += a1.x; hi1.y += a1.y; hi1.z += a1.z; hi1.w += a1.w;
        lo0.x += b0.x; lo0.y += b0.y; lo0.z += b0.z; lo0.w += b0.w;
        lo1.x += b1.x; lo1.y += b1.y; lo1.z += b1.z; lo1.w += b1.w;
        sden += base[64 + h] + base[144 + h];
        deg  += base[72] + base[152];
    }

    const float e = expf(g_el[h * NN + n]);
    const float denom = (float)NN - deg + e * sden;
    const float r = e / denom;

    float v[8];
    v[0] = (hi0.x + lo0.x) * r; v[1] = (hi0.y + lo0.y) * r;
    v[2] = (hi0.z + lo0.z) * r; v[3] = (hi0.w + lo0.w) * r;
    v[4] = (hi1.x + lo1.x) * r; v[5] = (hi1.y + lo1.y) * r;
    v[6] = (hi1.z + lo1.z) * r; v[7] = (hi1.w + lo1.w) * r;

    float4 o0, o1;
    o0.x = v[0] > 0.f ? v[0] : expm1f(v[0]);
    o0.y = v[1] > 0.f ? v[1] : expm1f(v[1]);
    o0.z = v[2] > 0.f ? v[2] : expm1f(v[2]);
    o0.w = v[3] > 0.f ? v[3] : expm1f(v[3]);
    o1.x = v[4] > 0.f ? v[4] : expm1f(v[4]);
    o1.y = v[5] > 0.f ? v[5] : expm1f(v[5]);
    o1.z = v[6] > 0.f ? v[6] : expm1f(v[6]);
    o1.w = v[7] > 0.f ? v[7] : expm1f(v[7]);

    float4* op = reinterpret_cast<float4*>(out + (size_t)n * (HEADS * UU) + h * 8);
    op[0] = o0;
    op[1] = o1;
}

// ---------------- launcher ----------------
extern "C" void kernel_launch(void* const* d_in, const int* in_sizes, int n_in,
                              void* d_out, int out_size)
{
    (void)in_sizes; (void)n_in; (void)out_size;
    const float* A  = (const float*)d_in[0];
    const float* H  = (const float*)d_in[1];
    const float* W  = (const float*)d_in[2];
    const float* al = (const float*)d_in[3];
    const float* ar = (const float*)d_in[4];
    float* out = (float*)d_out;

    cudaFuncSetAttribute(gat_build, cudaFuncAttributeMaxDynamicSharedMemorySize, BUILD_SMEM);

    gat_build<<<NN / 32, 512, BUILD_SMEM>>>(H, W, al, ar);
    dim3 gg(NN / MT, KSPLIT);
    gat_gemm<<<gg, 256>>>(A);
    gat_epilogue<<<NN * HEADS / 256, 256>>>(out);
}